// round 1
// baseline (speedup 1.0000x reference)
#include <cuda_runtime.h>

#define NL 128   // rows of lines tables
#define CL 32    // embedding width
#define HD 128   // hidden dim
#define NFLAG (3 * NL)

// Persistent device scratch (no allocations allowed).
__device__ unsigned int g_flags[NFLAG];
__device__ float g_c0;

// ---------------------------------------------------------------------------
// Kernel A: reset occupancy flags, compute tail constant c0 = w2·relu(b1)+b2
// ---------------------------------------------------------------------------
__global__ void k_init(const float* __restrict__ b1,
                       const float* __restrict__ w2,
                       const float* __restrict__ b2) {
    int t = threadIdx.x;
    if (t < NFLAG) g_flags[t] = 0u;

    __shared__ float part[4];
    float v = 0.f;
    if (t < HD) v = fmaxf(b1[t], 0.f) * w2[t];
    #pragma unroll
    for (int o = 16; o; o >>= 1) v += __shfl_down_sync(0xffffffffu, v, o);
    if (t < HD && (t & 31) == 0) part[t >> 5] = v;
    __syncthreads();
    if (t == 0) g_c0 = part[0] + part[1] + part[2] + part[3] + b2[0];
}

// ---------------------------------------------------------------------------
// Kernel B: scan coordinates -> occupancy flags; fill out[NL..N) with c0.
//
// Layout: coords are a flat float stream; element at flat index f belongs to
// axis f % 3. Warps consume 96 consecutive float4s (384 floats): lane l loads
// c4[base+l], c4[base+32+l], c4[base+64+l] (perfectly coalesced LDG.128).
// Since base % 3 == 0, the axis of slot (s, i) for lane l is
// (l + 2s + i) % 3 — select among 3 per-lane precomputed flag-base registers.
//
// k = round((v+2)*32) computed as __float2int_rn(fmaf(v, 32, 64)): bit-exact
// vs the reference (power-of-two scaling commutes with fp32 rounding;
// round-half-even in both).
// ---------------------------------------------------------------------------
__global__ __launch_bounds__(256) void k_scan(const float4* __restrict__ c4,
                                              long long n128,
                                              const float* __restrict__ cflat,
                                              long long nfloats,
                                              float* __restrict__ out,
                                              long long nout) {
    __shared__ unsigned int sflag[NFLAG];
    const int tid = threadIdx.x;
    for (int i = tid; i < NFLAG; i += blockDim.x) sflag[i] = 0u;
    __syncthreads();

    const int lane = tid & 31;
    // Flag-base registers: Bj = base offset for axis (lane + j) % 3
    int d0 = lane % 3;
    int d1 = d0 + 1; if (d1 == 3) d1 = 0;
    int d2 = d1 + 1; if (d2 == 3) d2 = 0;
    const unsigned B0 = (unsigned)d0 * NL;
    const unsigned B1r = (unsigned)d1 * NL;
    const unsigned B2r = (unsigned)d2 * NL;

#define PROC(v, BB)                                                  \
    {                                                                \
        float t_ = fmaf((v), 32.0f, 64.0f);                          \
        int k_ = __float2int_rn(t_);                                 \
        if ((unsigned)k_ < (unsigned)NL) sflag[(BB) + k_] = 1u;      \
    }

    const long long nwarps = (long long)gridDim.x * (blockDim.x >> 5);
    const long long wg = (long long)blockIdx.x * (blockDim.x >> 5) + (tid >> 5);
    const long long nchunks = n128 / 96;

    for (long long w = wg; w < nchunks; w += nwarps) {
        const long long base = w * 96 + lane;
        float4 f0 = c4[base];
        float4 f1 = c4[base + 32];
        float4 f2 = c4[base + 64];
        // s=0: j = i%3
        PROC(f0.x, B0) PROC(f0.y, B1r) PROC(f0.z, B2r) PROC(f0.w, B0)
        // s=1: j = (i+2)%3
        PROC(f1.x, B2r) PROC(f1.y, B0) PROC(f1.z, B1r) PROC(f1.w, B2r)
        // s=2: j = (i+1)%3
        PROC(f2.x, B1r) PROC(f2.y, B2r) PROC(f2.z, B0) PROC(f2.w, B1r)
    }

    // Tail float4s (n128 % 96) — runtime axis computation.
    const long long gid = (long long)blockIdx.x * blockDim.x + tid;
    const long long gsz = (long long)gridDim.x * blockDim.x;
    for (long long q = nchunks * 96 + gid; q < n128; q += gsz) {
        float4 f = c4[q];
        int db = (int)((q << 2) % 3);
        float vv[4] = {f.x, f.y, f.z, f.w};
        #pragma unroll
        for (int i = 0; i < 4; i++) {
            int d = db + i; if (d >= 3) d -= 3; if (d >= 3) d -= 3;
            float t_ = fmaf(vv[i], 32.0f, 64.0f);
            int k_ = __float2int_rn(t_);
            if ((unsigned)k_ < (unsigned)NL) sflag[d * NL + k_] = 1u;
        }
    }
    // Scalar tail (nfloats % 4) — not hit for these shapes, kept for safety.
    for (long long q = (n128 << 2) + gid; q < nfloats; q += gsz) {
        int d = (int)(q % 3);
        float t_ = fmaf(cflat[q], 32.0f, 64.0f);
        int k_ = __float2int_rn(t_);
        if ((unsigned)k_ < (unsigned)NL) sflag[d * NL + k_] = 1u;
    }
#undef PROC

    __syncthreads();
    for (int i = tid; i < NFLAG; i += blockDim.x)
        if (sflag[i]) g_flags[i] = 1u;  // benign race: all writers store 1

    // Fill out[NL .. nout) with c0 (vectorized).
    const float c0 = g_c0;
    const float4 cv = make_float4(c0, c0, c0, c0);
    float4* out4 = (float4*)out;
    const long long n4 = nout >> 2;
    for (long long q = (NL / 4) + gid; q < n4; q += gsz) out4[q] = cv;
    for (long long q = (n4 << 2) + gid; q < nout; q += gsz)
        if (q >= NL) out[q] = c0;
}

// ---------------------------------------------------------------------------
// Kernel C: head rows r in [0, NL). One block per row, HD threads.
// ---------------------------------------------------------------------------
__global__ __launch_bounds__(HD) void k_head(const float* __restrict__ lines0,
                                             const float* __restrict__ lines1,
                                             const float* __restrict__ lines2,
                                             const float* __restrict__ w1,
                                             const float* __restrict__ b1,
                                             const float* __restrict__ w2,
                                             const float* __restrict__ b2,
                                             float* __restrict__ out,
                                             long long nout) {
    __shared__ float s_w1[HD * (CL + 1)];  // padded: bank (j + c) % 32
    __shared__ float s_feats[CL];
    __shared__ float s_part[4];

    const int r = blockIdx.x;
    const int j = threadIdx.x;

    // Stage w1 coalesced.
    for (int t = j; t < HD * CL; t += HD)
        s_w1[(t >> 5) * (CL + 1) + (t & 31)] = w1[t];

    if (j < CL) {
        float fx = g_flags[r]          ? 1.f : 0.f;
        float fy = g_flags[NL + r]     ? 1.f : 0.f;
        float fz = g_flags[2 * NL + r] ? 1.f : 0.f;
        float x = lines0[r * CL + j] * fx;
        float y = lines1[r * CL + j] * fy;
        float z = lines2[r * CL + j] * fz;
        float f1 = x + y + z;
        float f2 = (x * y + x * z + y * z) / 0.4f;
        float f3 = x * y * z / 0.16000000000000003f;
        s_feats[j] = f1 + f2 + f3;
    }
    __syncthreads();

    float acc = b1[j];
    #pragma unroll
    for (int c = 0; c < CL; c++)
        acc += s_feats[c] * s_w1[j * (CL + 1) + c];
    float term = fmaxf(acc, 0.f) * w2[j];
    #pragma unroll
    for (int o = 16; o; o >>= 1) term += __shfl_down_sync(0xffffffffu, term, o);
    if ((j & 31) == 0) s_part[j >> 5] = term;
    __syncthreads();
    if (j == 0 && r < nout)
        out[r] = s_part[0] + s_part[1] + s_part[2] + s_part[3] + b2[0];
}

// ---------------------------------------------------------------------------
extern "C" void kernel_launch(void* const* d_in, const int* in_sizes, int n_in,
                              void* d_out, int out_size) {
    const float* coords = (const float*)d_in[0];
    const float* lines0 = (const float*)d_in[1];
    const float* lines1 = (const float*)d_in[2];
    const float* lines2 = (const float*)d_in[3];
    const float* w1     = (const float*)d_in[4];
    const float* b1     = (const float*)d_in[5];
    const float* w2     = (const float*)d_in[6];
    const float* b2     = (const float*)d_in[7];
    float* out = (float*)d_out;

    const long long nfloats = in_sizes[0];
    const long long n128 = nfloats >> 2;

    k_init<<<1, 512>>>(b1, w2, b2);
    k_scan<<<1184, 256>>>((const float4*)coords, n128, coords, nfloats,
                          out, (long long)out_size);
    k_head<<<NL, HD>>>(lines0, lines1, lines2, w1, b1, w2, b2,
                       out, (long long)out_size);
}